// round 3
// baseline (speedup 1.0000x reference)
#include <cuda_runtime.h>
#include <math_constants.h>

// MSE+BPR pairwise loss, N=16384.
// total = sum over ordered pairs (i,j) with t[j] > t[i] of
//         0.5*softplus(in[i]-in[j]) + 0.5*(in[i]-t[i])^2
// out = total * 2/N^2
//
// Strategy: enumerate unordered pairs {i,j} (i<j) in 256x256 tiles; exactly one
// direction contributes per pair (none on target ties). softplus(d) =
// max(d,0) + ln2*log2(1+exp(-|d|)); the log term is direction-independent.
// Per-thread fp32 partials -> double block reduction -> atomicAdd(double).

#define TILE 256

__device__ double g_accum;

__global__ void mb_zero_kernel() { g_accum = 0.0; }

__global__ void mb_finalize_kernel(float* out, int n) {
    double scale = 2.0 / ((double)n * (double)n);
    out[0] = (float)(g_accum * scale);
}

__global__ void __launch_bounds__(TILE)
mb_pair_kernel(const float* __restrict__ inp,
               const float* __restrict__ tgt,
               int n) {
    const int bi = blockIdx.y;   // row tile
    const int bj = blockIdx.x;   // col tile
    if (bi > bj) return;         // only upper-triangular tiles (all threads exit)

    __shared__ float4 sc[TILE];      // {x_j, t_j, mse_j, pad}
    __shared__ double red[TILE];

    const int tid = threadIdx.x;
    const int ig = bi * TILE + tid;
    const int jg = bj * TILE + tid;

    // Row-resident data (this thread's i). Pad with NaN target: all compares false.
    float xi = 0.0f, ti = CUDART_NAN_F, mi = 0.0f;
    if (ig < n) {
        xi = inp[ig];
        ti = tgt[ig];
        float dm = xi - ti;
        mi = dm * dm;
    }
    // Column data -> shared (cooperative).
    float xj = 0.0f, tj = CUDART_NAN_F, mj = 0.0f;
    if (jg < n) {
        xj = inp[jg];
        tj = tgt[jg];
        float dm = xj - tj;
        mj = dm * dm;
    }
    sc[tid] = make_float4(xj, tj, mj, 0.0f);
    __syncthreads();

    float acc_l2  = 0.0f;   // sum of log2(1 + exp(-|d|)) over valid pairs
    float acc_lin = 0.0f;   // sum of relu(directed d) over valid pairs
    float cnt     = 0.0f;   // # pairs where this row's mse contributes (t_j > t_i)
    float acc_mj  = 0.0f;   // sum of column mse where t_i > t_j

    if (bi != bj) {
        // Full 256x256 tile: every (i,j) is a distinct unordered pair.
        #pragma unroll 8
        for (int j = 0; j < TILE; ++j) {
            float4 c = sc[j];
            float d0 = xi - c.x;                       // in_i - in_j
            float e  = __expf(-fabsf(d0));             // FMUL + MUFU.EX2
            float l2 = __log2f(1.0f + e);              // FADD + MUFU.LG2
            bool m1 = c.y > ti;                        // t_j > t_i -> direction i->j
            bool m2 = ti  > c.y;                       // t_i > t_j -> direction j->i
            float rp = fmaxf(m1 ? d0 : -d0, 0.0f);
            if (m1 | m2) { acc_l2 += l2; acc_lin += rp; }
            if (m1) cnt += 1.0f;
            if (m2) acc_mj += c.z;
        }
    } else {
        // Diagonal tile: only j > i (strict upper triangle within the tile).
        #pragma unroll 4
        for (int j = tid + 1; j < TILE; ++j) {
            float4 c = sc[j];
            float d0 = xi - c.x;
            float e  = __expf(-fabsf(d0));
            float l2 = __log2f(1.0f + e);
            bool m1 = c.y > ti;
            bool m2 = ti  > c.y;
            float rp = fmaxf(m1 ? d0 : -d0, 0.0f);
            if (m1 | m2) { acc_l2 += l2; acc_lin += rp; }
            if (m1) cnt += 1.0f;
            if (m2) acc_mj += c.z;
        }
    }

    // Per-thread partial in double:
    // 0.5*(relu + ln2*log2sum)  [BPR]  +  0.5*(cnt*mse_i + sum mse_j) [MSE]
    double part = 0.5 * ((double)acc_lin + (double)acc_l2 * 0.69314718055994530942)
                + 0.5 * ((double)cnt * (double)mi + (double)acc_mj);

    red[tid] = part;
    __syncthreads();
    #pragma unroll
    for (int s = TILE / 2; s > 0; s >>= 1) {
        if (tid < s) red[tid] += red[tid + s];
        __syncthreads();
    }
    if (tid == 0) atomicAdd(&g_accum, red[0]);
}

extern "C" void kernel_launch(void* const* d_in, const int* in_sizes, int n_in,
                              void* d_out, int out_size) {
    const float* inp = (const float*)d_in[0];
    const float* tgt = (const float*)d_in[1];
    float* out = (float*)d_out;
    int n = in_sizes[0];

    int nb = (n + TILE - 1) / TILE;
    dim3 grid(nb, nb);

    mb_zero_kernel<<<1, 1>>>();
    mb_pair_kernel<<<grid, TILE>>>(inp, tgt, n);
    mb_finalize_kernel<<<1, 1>>>(out, n);
}